// round 16
// baseline (speedup 1.0000x reference)
#include <cuda_runtime.h>

#define NCOLS  8192
#define NWIN   513
#define NT     256
#define KPT    32

#define TLO (-1.31f)
#define THI ( 1.31f)
#define FINF  __int_as_float(0x7f800000)
#define FNINF __int_as_float(0xff800000)

__device__ __forceinline__ unsigned f2key(float x) {
    unsigned u = __float_as_uint(x);
    return (u & 0x80000000u) ? ~u : (u | 0x80000000u);
}
__device__ __forceinline__ float key2f(unsigned k) {
    unsigned u = (k & 0x80000000u) ? (k ^ 0x80000000u) : ~k;
    return __uint_as_float(u);
}

__device__ __forceinline__ void casf(float& a, float& b, bool up) {
    float lo = up ? fminf(a, b) : fmaxf(a, b);
    float hi = up ? fmaxf(a, b) : fminf(a, b);
    a = lo; b = hi;
}

__device__ __forceinline__ void sort8f(float v[8], bool up) {
    casf(v[0], v[4], up); casf(v[1], v[5], up); casf(v[2], v[6], up); casf(v[3], v[7], up);
    casf(v[0], v[2], up); casf(v[1], v[3], up); casf(v[4], v[6], up); casf(v[5], v[7], up);
    casf(v[0], v[1], up); casf(v[2], v[3], up); casf(v[4], v[5], up); casf(v[6], v[7], up);
}

__device__ __forceinline__ void batcher8f(float v[8], bool up) {
    casf(v[0], v[1], up); casf(v[2], v[3], up); casf(v[4], v[5], up); casf(v[6], v[7], up);
    casf(v[0], v[2], up); casf(v[1], v[3], up); casf(v[4], v[6], up); casf(v[5], v[7], up);
    casf(v[1], v[2], up); casf(v[5], v[6], up);
    casf(v[0], v[4], up); casf(v[1], v[5], up); casf(v[2], v[6], up); casf(v[3], v[7], up);
    casf(v[2], v[4], up); casf(v[3], v[5], up);
    casf(v[1], v[2], up); casf(v[3], v[4], up); casf(v[5], v[6], up);
}

// dual-row pass: 16 independent chains per warp hide SHFL/FMNMX latency
__device__ __forceinline__ void shfl_pass2(float vA[8], float vB[8],
                                           int delta, bool up, int ts) {
    bool keepmin = (up == ((ts & delta) == 0));
    #pragma unroll
    for (int e = 0; e < 8; ++e) {
        float oA = __shfl_xor_sync(0xffffffffu, vA[e], delta);
        float oB = __shfl_xor_sync(0xffffffffu, vB[e], delta);
        vA[e] = keepmin ? fminf(vA[e], oA) : fmaxf(vA[e], oA);
        vB[e] = keepmin ? fminf(vB[e], oB) : fmaxf(vB[e], oB);
    }
}

// one barrier pair serves both rows
__device__ __forceinline__ void smem_pass2(float vA[8], float vB[8],
                                           int delta, bool up, int t, int ts,
                                           float* sA, float* sB) {
    __syncthreads();
    #pragma unroll
    for (int e = 0; e < 8; ++e) { sA[t * 8 + e] = vA[e]; sB[t * 8 + e] = vB[e]; }
    __syncthreads();
    bool keepmin = (up == ((ts & delta) == 0));
    int pt = t ^ delta;
    if (keepmin) {
        #pragma unroll
        for (int e = 0; e < 8; ++e) {
            vA[e] = fminf(vA[e], sA[pt * 8 + e]);
            vB[e] = fminf(vB[e], sB[pt * 8 + e]);
        }
    } else {
        #pragma unroll
        for (int e = 0; e < 8; ++e) {
            vA[e] = fmaxf(vA[e], sA[pt * 8 + e]);
            vB[e] = fmaxf(vB[e], sB[pt * 8 + e]);
        }
    }
}

// ---- exact fallback helpers (f2key domain; block-uniform; cold) ----
__device__ unsigned block_count(const float4* x4, unsigned K, bool ge,
                                unsigned* s_red, int tid) {
    if (tid == 0) *s_red = 0;
    __syncthreads();
    unsigned c = 0;
    for (int i = tid; i < NCOLS / 4; i += NT) {
        float4 w = x4[i];
        unsigned k0 = f2key(w.x), k1 = f2key(w.y), k2 = f2key(w.z), k3 = f2key(w.w);
        if (ge) c += (k0 >= K) + (k1 >= K) + (k2 >= K) + (k3 >= K);
        else    c += (k0 <= K) + (k1 <= K) + (k2 <= K) + (k3 <= K);
    }
    #pragma unroll
    for (int off = 16; off; off >>= 1) c += __shfl_down_sync(0xffffffffu, c, off);
    if ((tid & 31) == 0) atomicAdd(s_red, c);
    __syncthreads();
    unsigned r = *s_red;
    __syncthreads();
    return r;
}

__device__ unsigned gather_side(const float4* x4, unsigned T, int side,
                                float* seg, unsigned* s_c, int tid) {
    if (tid == 0) *s_c = 0;
    __syncthreads();
    const int lane = tid & 31;
    for (int i = tid; i < NCOLS / 4; i += NT) {
        float4 w = x4[i];
        unsigned kk[4] = { f2key(w.x), f2key(w.y), f2key(w.z), f2key(w.w) };
        #pragma unroll
        for (int q = 0; q < 4; ++q) {
            bool take = side ? (kk[q] > T) : (kk[q] < T);
            unsigned m = __ballot_sync(0xffffffffu, take);
            unsigned base = 0;
            if (lane == 0 && m) base = atomicAdd(s_c, (unsigned)__popc(m));
            base = __shfl_sync(0xffffffffu, base, 0);
            if (take) {
                unsigned p = base + __popc(m & ((1u << lane) - 1u));
                if (p < 1024) seg[p] = key2f(kk[q]);
            }
        }
    }
    __syncthreads();
    unsigned r = *s_c;
    __syncthreads();
    return r;
}

// exact per-side fallback: select rank key, regather, pad (cold)
__device__ unsigned exact_side(const float4* x4, int side, float* seg,
                               unsigned* s_c, int t) {
    unsigned c;
    if (side == 0) {
        unsigned Kcut;
        if (block_count(x4, 0u, false, s_c, t) >= 513u) {
            Kcut = 0u;
        } else {
            unsigned X = 0;
            for (int b = 31; b >= 0; --b) {
                unsigned X2 = X | (1u << b);
                if (block_count(x4, X2, false, s_c, t) < 513u) X = X2;
            }
            Kcut = X + 1u;
        }
        c = gather_side(x4, Kcut, 0, seg, s_c, t);
        float fK = key2f(Kcut);
        for (int i = (int)c + t; i < 513; i += NT) seg[i] = fK;
    } else {
        unsigned Y = 0;
        for (int b = 31; b >= 0; --b) {
            unsigned Y2 = Y | (1u << b);
            if (block_count(x4, Y2, true, s_c, t) >= 513u) Y = Y2;
        }
        c = gather_side(x4, Y, 1, seg, s_c, t);
        float fY = key2f(Y);
        for (int i = (int)c + t; i < 513; i += NT) seg[i] = fY;
    }
    return 513u;
}

__global__ __launch_bounds__(NT, 4)
void recall_window_kernel(const float* __restrict__ x,
                          float* __restrict__ out, int rows)
{
    // row A: lo [0,1024) hi [1024,2048); row B: lo [2048,3072) hi [3072,4096)
    __shared__ float    scratch[4096];
    __shared__ unsigned wsA[8], wsB[8];
    __shared__ float    wredA[8], wredB[8];
    __shared__ unsigned s_c;
    __shared__ unsigned long long s_best[2];

    const int t    = threadIdx.x;
    const int lane = t & 31;
    const int wid  = t >> 5;
    const int ts   = t & 127;
    const int rowA = 2 * blockIdx.x;
    const int rowB = rowA + 1;
    const float4* x4A = reinterpret_cast<const float4*>(x + (size_t)rowA * NCOLS);
    const float4* x4B = reinterpret_cast<const float4*>(x + (size_t)rowB * NCOLS);
    float* sA = scratch;
    float* sB = scratch + 2048;

    // ---- phase 1: count tail takes for both rows ----
    unsigned cloA = 0, chiA = 0, cloB = 0, chiB = 0;
    #pragma unroll
    for (int e4 = 0; e4 < KPT / 4; ++e4) {
        float4 wA = x4A[e4 * NT + t];
        float4 wB = x4B[e4 * NT + t];
        cloA += (wA.x < TLO) + (wA.y < TLO) + (wA.z < TLO) + (wA.w < TLO);
        chiA += (wA.x > THI) + (wA.y > THI) + (wA.z > THI) + (wA.w > THI);
        cloB += (wB.x < TLO) + (wB.y < TLO) + (wB.z < TLO) + (wB.w < TLO);
        chiB += (wB.x > THI) + (wB.y > THI) + (wB.z > THI) + (wB.w > THI);
    }

    // ---- phase 2: two packed block scans (interleaved) ----
    unsigned pA = cloA | (chiA << 16);
    unsigned pB = cloB | (chiB << 16);
    unsigned iA = pA, iB = pB;
    #pragma unroll
    for (int off = 1; off < 32; off <<= 1) {
        unsigned vA_ = __shfl_up_sync(0xffffffffu, iA, off);
        unsigned vB_ = __shfl_up_sync(0xffffffffu, iB, off);
        if (lane >= off) { iA += vA_; iB += vB_; }
    }
    if (lane == 31) { wsA[wid] = iA; wsB[wid] = iB; }
    __syncthreads();
    unsigned wbA = 0, totA = 0, wbB = 0, totB = 0;
    #pragma unroll
    for (int w = 0; w < 8; ++w) {
        unsigned sa = wsA[w], sb = wsB[w];
        wbA += (w < wid) ? sa : 0u;  totA += sa;
        wbB += (w < wid) ? sb : 0u;  totB += sb;
    }
    unsigned exA = wbA + iA - pA, exB = wbB + iB - pB;
    unsigned baseloA = exA & 0xFFFFu, basehiA = exA >> 16;
    unsigned baseloB = exB & 0xFFFFu, basehiB = exB >> 16;
    unsigned totloA = totA & 0xFFFFu, tothiA = totA >> 16;
    unsigned totloB = totB & 0xFFFFu, tothiB = totB >> 16;

    const bool okAlo = (totloA >= 513u && totloA <= 1024u);
    const bool okAhi = (tothiA >= 513u && tothiA <= 1024u);
    const bool okBlo = (totloB >= 513u && totloB <= 1024u);
    const bool okBhi = (tothiB >= 513u && tothiB <= 1024u);

    // ---- phase 3: re-read rows (cache-hot), scatter ----
    if (okAlo && okAhi) {
        unsigned plo = baseloA, phi = basehiA;
        #pragma unroll
        for (int e4 = 0; e4 < KPT / 4; ++e4) {
            float4 w = x4A[e4 * NT + t];
            float fa[4] = { w.x, w.y, w.z, w.w };
            #pragma unroll
            for (int q = 0; q < 4; ++q) {
                float f = fa[q];
                if (f < TLO)      sA[plo++] = f;
                else if (f > THI) sA[1024 + phi++] = f;
            }
        }
    }
    if (okBlo && okBhi) {
        unsigned plo = baseloB, phi = basehiB;
        #pragma unroll
        for (int e4 = 0; e4 < KPT / 4; ++e4) {
            float4 w = x4B[e4 * NT + t];
            float fa[4] = { w.x, w.y, w.z, w.w };
            #pragma unroll
            for (int q = 0; q < 4; ++q) {
                float f = fa[q];
                if (f < TLO)      sB[plo++] = f;
                else if (f > THI) sB[1024 + phi++] = f;
            }
        }
    }
    __syncthreads();

    unsigned c0A = totloA, c1A = tothiA, c0B = totloB, c1B = tothiB;
    if (!okAlo) c0A = exact_side(x4A, 0, sA,        &s_c, t);
    if (!okAhi) c1A = exact_side(x4A, 1, sA + 1024, &s_c, t);
    if (!okBlo) c0B = exact_side(x4B, 0, sB,        &s_c, t);
    if (!okBhi) c1B = exact_side(x4B, 1, sB + 1024, &s_c, t);

    for (int i = (int)c0A + t; i < 1024; i += NT) sA[i]        = FINF;
    for (int i = (int)c1A + t; i < 1024; i += NT) sA[1024 + i] = FNINF;
    for (int i = (int)c0B + t; i < 1024; i += NT) sB[i]        = FINF;
    for (int i = (int)c1B + t; i < 1024; i += NT) sB[1024 + i] = FNINF;
    if (t == 0) { s_best[0] = ~0ull; s_best[1] = ~0ull; }
    __syncthreads();

    // ---- phase 4: dual-row register-blocked bitonic ----
    float vA[8], vB[8];
    #pragma unroll
    for (int e = 0; e < 8; ++e) { vA[e] = sA[t * 8 + e]; vB[e] = sB[t * 8 + e]; }

    batcher8f(vA, (ts & 1) == 0);
    batcher8f(vB, (ts & 1) == 0);

    #pragma unroll
    for (int kk = 16; kk <= 512; kk <<= 1) {
        bool up = ((ts & (kk >> 3)) == 0);
        #pragma unroll
        for (int j = kk >> 1; j >= 8; j >>= 1) {
            int delta = j >> 3;
            if (delta >= 32) smem_pass2(vA, vB, delta, up, t, ts, sA, sB);
            else             shfl_pass2(vA, vB, delta, up, ts);
        }
        sort8f(vA, up);
        sort8f(vB, up);
    }

    // ---- final merge kk=1024 (up), pruned as in R15, dual-row ----
    smem_pass2(vA, vB, 64, true, t, ts, sA, sB);    // separation

    const bool need = (t < 128) ? (ts < 64) : (ts >= 64);   // warp-uniform

    float redA = 0.0f, redB = 0.0f;
    if (!need) {
        if (t < 128) {       // lo top halves -> boundary mins
            redA = fminf(fminf(fminf(vA[0], vA[1]), fminf(vA[2], vA[3])),
                         fminf(fminf(vA[4], vA[5]), fminf(vA[6], vA[7])));
            redB = fminf(fminf(fminf(vB[0], vB[1]), fminf(vB[2], vB[3])),
                         fminf(fminf(vB[4], vB[5]), fminf(vB[6], vB[7])));
            #pragma unroll
            for (int off = 16; off; off >>= 1) {
                redA = fminf(redA, __shfl_xor_sync(0xffffffffu, redA, off));
                redB = fminf(redB, __shfl_xor_sync(0xffffffffu, redB, off));
            }
        } else {             // hi bottom halves -> boundary maxes
            redA = fmaxf(fmaxf(fmaxf(vA[0], vA[1]), fmaxf(vA[2], vA[3])),
                         fmaxf(fmaxf(vA[4], vA[5]), fmaxf(vA[6], vA[7])));
            redB = fmaxf(fmaxf(fmaxf(vB[0], vB[1]), fmaxf(vB[2], vB[3])),
                         fmaxf(fmaxf(vB[4], vB[5]), fmaxf(vB[6], vB[7])));
            #pragma unroll
            for (int off = 16; off; off >>= 1) {
                redA = fmaxf(redA, __shfl_xor_sync(0xffffffffu, redA, off));
                redB = fmaxf(redB, __shfl_xor_sync(0xffffffffu, redB, off));
            }
        }
    }

    __syncthreads();
    if (need) {
        #pragma unroll
        for (int e = 0; e < 8; ++e) { sA[t * 8 + e] = vA[e]; sB[t * 8 + e] = vB[e]; }
    }
    __syncthreads();
    if (need) {
        bool keepmin = ((ts & 32) == 0);            // warp-uniform
        int pt = t ^ 32;
        if (keepmin) {
            #pragma unroll
            for (int e = 0; e < 8; ++e) {
                vA[e] = fminf(vA[e], sA[pt * 8 + e]);
                vB[e] = fminf(vB[e], sB[pt * 8 + e]);
            }
        } else {
            #pragma unroll
            for (int e = 0; e < 8; ++e) {
                vA[e] = fmaxf(vA[e], sA[pt * 8 + e]);
                vB[e] = fmaxf(vB[e], sB[pt * 8 + e]);
            }
        }
        shfl_pass2(vA, vB, 16, true, ts);
        shfl_pass2(vA, vB,  8, true, ts);
        shfl_pass2(vA, vB,  4, true, ts);
        shfl_pass2(vA, vB,  2, true, ts);
        shfl_pass2(vA, vB,  1, true, ts);
        sort8f(vA, true);
        sort8f(vB, true);
    }

    __syncthreads();
    #pragma unroll
    for (int e = 0; e < 8; ++e) { sA[t * 8 + e] = vA[e]; sB[t * 8 + e] = vB[e]; }
    if (!need && lane == 0) { wredA[wid] = redA; wredB[wid] = redB; }
    __syncthreads();
    if (t == 0) {
        sA[512]  = fminf(wredA[2], wredA[3]);   // A lo s[512]
        sA[1535] = fmaxf(wredA[4], wredA[5]);   // A hi s[511]
        sB[512]  = fminf(wredB[2], wredB[3]);
        sB[1535] = fmaxf(wredB[4], wredB[5]);
    }
    __syncthreads();

    // ---- phase 5: dual argmin ----
    unsigned long long bestA = ~0ull, bestB = ~0ull;
    for (int i = t; i < NWIN; i += NT) {
        float lenA = sA[1535 + i] - sA[i];
        float lenB = sB[1535 + i] - sB[i];
        unsigned long long pa =
            ((unsigned long long)__float_as_uint(lenA) << 32) | (unsigned)i;
        unsigned long long pb =
            ((unsigned long long)__float_as_uint(lenB) << 32) | (unsigned)i;
        bestA = (pa < bestA) ? pa : bestA;
        bestB = (pb < bestB) ? pb : bestB;
    }
    #pragma unroll
    for (int off = 16; off; off >>= 1) {
        unsigned long long oa = __shfl_down_sync(0xffffffffu, bestA, off);
        unsigned long long ob = __shfl_down_sync(0xffffffffu, bestB, off);
        bestA = (oa < bestA) ? oa : bestA;
        bestB = (ob < bestB) ? ob : bestB;
    }
    if (lane == 0) {
        atomicMin(&s_best[0], bestA);
        atomicMin(&s_best[1], bestB);
    }
    __syncthreads();

    if (t == 0) {
        int iA = (int)(unsigned)(s_best[0] & 0xffffffffu);
        int iB = (int)(unsigned)(s_best[1] & 0xffffffffu);
        out[rowA]        = sA[iA];
        out[rows + rowA] = sA[1535 + iA];
        out[rowB]        = sB[iB];
        out[rows + rowB] = sB[1535 + iB];
    }
}

extern "C" void kernel_launch(void* const* d_in, const int* in_sizes, int n_in,
                              void* d_out, int out_size) {
    const float* x = (const float*)d_in[0];
    float* out = (float*)d_out;
    int rows = in_sizes[0] / NCOLS;   // 4096
    recall_window_kernel<<<rows / 2, NT>>>(x, out, rows);
}

// round 17
// speedup vs baseline: 1.4473x; 1.4473x over previous
#include <cuda_runtime.h>

#define NCOLS  8192
#define NWIN   513
#define NT     256
#define KPT    32

#define TLO (-1.31f)
#define THI ( 1.31f)
#define FINF  __int_as_float(0x7f800000)
#define FNINF __int_as_float(0xff800000)

__device__ __forceinline__ unsigned f2key(float x) {
    unsigned u = __float_as_uint(x);
    return (u & 0x80000000u) ? ~u : (u | 0x80000000u);
}
__device__ __forceinline__ float key2f(unsigned k) {
    unsigned u = (k & 0x80000000u) ? (k ^ 0x80000000u) : ~k;
    return __uint_as_float(u);
}

__device__ __forceinline__ void casf(float& a, float& b, bool up) {
    float lo = up ? fminf(a, b) : fmaxf(a, b);
    float hi = up ? fmaxf(a, b) : fminf(a, b);
    a = lo; b = hi;
}

// bitonic-merge step for 8 regs
__device__ __forceinline__ void sort8f(float v[8], bool up) {
    casf(v[0], v[4], up); casf(v[1], v[5], up); casf(v[2], v[6], up); casf(v[3], v[7], up);
    casf(v[0], v[2], up); casf(v[1], v[3], up); casf(v[4], v[6], up); casf(v[5], v[7], up);
    casf(v[0], v[1], up); casf(v[2], v[3], up); casf(v[4], v[5], up); casf(v[6], v[7], up);
}

// Batcher odd-even 8-sort: 19 comparators.
__device__ __forceinline__ void batcher8f(float v[8], bool up) {
    casf(v[0], v[1], up); casf(v[2], v[3], up); casf(v[4], v[5], up); casf(v[6], v[7], up);
    casf(v[0], v[2], up); casf(v[1], v[3], up); casf(v[4], v[6], up); casf(v[5], v[7], up);
    casf(v[1], v[2], up); casf(v[5], v[6], up);
    casf(v[0], v[4], up); casf(v[1], v[5], up); casf(v[2], v[6], up); casf(v[3], v[7], up);
    casf(v[2], v[4], up); casf(v[3], v[5], up);
    casf(v[1], v[2], up); casf(v[3], v[4], up); casf(v[5], v[6], up);
}

// BRANCHLESS predication (ternary, not if — R5 proof).
__device__ __forceinline__ void shfl_pass(float v[8], int delta, bool up, int ts) {
    bool keepmin = (up == ((ts & delta) == 0));
    #pragma unroll
    for (int e = 0; e < 8; ++e) {
        float o = __shfl_xor_sync(0xffffffffu, v[e], delta);
        v[e] = keepmin ? fminf(v[e], o) : fmaxf(v[e], o);
    }
}

// delta >= 32: warp-uniform keepmin. SoA staging scratch[e*256+t]:
// for fixed e, lane addresses are consecutive -> conflict-free STS/LDS
// (the old t*8+e layout was 8-way bank conflicted on every access).
__device__ __forceinline__ void smem_pass(float v[8], int delta, bool up,
                                          int t, int ts, float* scratch) {
    __syncthreads();
    #pragma unroll
    for (int e = 0; e < 8; ++e) scratch[e * 256 + t] = v[e];
    __syncthreads();
    bool keepmin = (up == ((ts & delta) == 0));
    int pt = t ^ delta;
    if (keepmin) {
        #pragma unroll
        for (int e = 0; e < 8; ++e) v[e] = fminf(v[e], scratch[e * 256 + pt]);
    } else {
        #pragma unroll
        for (int e = 0; e < 8; ++e) v[e] = fmaxf(v[e], scratch[e * 256 + pt]);
    }
}

// ---- exact fallback helpers (f2key domain; block-uniform; cold) ----
__device__ unsigned block_count(const float4* x4, unsigned K, bool ge,
                                unsigned* s_red, int tid) {
    if (tid == 0) *s_red = 0;
    __syncthreads();
    unsigned c = 0;
    for (int i = tid; i < NCOLS / 4; i += NT) {
        float4 w = x4[i];
        unsigned k0 = f2key(w.x), k1 = f2key(w.y), k2 = f2key(w.z), k3 = f2key(w.w);
        if (ge) c += (k0 >= K) + (k1 >= K) + (k2 >= K) + (k3 >= K);
        else    c += (k0 <= K) + (k1 <= K) + (k2 <= K) + (k3 <= K);
    }
    #pragma unroll
    for (int off = 16; off; off >>= 1) c += __shfl_down_sync(0xffffffffu, c, off);
    if ((tid & 31) == 0) atomicAdd(s_red, c);
    __syncthreads();
    unsigned r = *s_red;
    __syncthreads();
    return r;
}

__device__ unsigned gather_side(const float4* x4, unsigned T, int side,
                                float* seg, unsigned* s_c, int tid) {
    if (tid == 0) *s_c = 0;
    __syncthreads();
    const int lane = tid & 31;
    for (int i = tid; i < NCOLS / 4; i += NT) {
        float4 w = x4[i];
        unsigned kk[4] = { f2key(w.x), f2key(w.y), f2key(w.z), f2key(w.w) };
        #pragma unroll
        for (int q = 0; q < 4; ++q) {
            bool take = side ? (kk[q] > T) : (kk[q] < T);
            unsigned m = __ballot_sync(0xffffffffu, take);
            unsigned base = 0;
            if (lane == 0 && m) base = atomicAdd(s_c, (unsigned)__popc(m));
            base = __shfl_sync(0xffffffffu, base, 0);
            if (take) {
                unsigned p = base + __popc(m & ((1u << lane) - 1u));
                if (p < 1024) seg[p] = key2f(kk[q]);
            }
        }
    }
    __syncthreads();
    unsigned r = *s_c;
    __syncthreads();
    return r;
}

__global__ __launch_bounds__(NT, 6)
void recall_window_kernel(const float* __restrict__ x,
                          float* __restrict__ out, int rows)
{
    __shared__ float    scratch[2048];
    __shared__ unsigned wsum[8];
    __shared__ float    wred[8];
    __shared__ unsigned s_c;
    __shared__ unsigned long long s_best;

    const int t    = threadIdx.x;
    const int lane = t & 31;
    const int wid  = t >> 5;
    const int ts   = t & 127;
    const int row  = blockIdx.x;
    const float4* x4 = reinterpret_cast<const float4*>(x + (size_t)row * NCOLS);

    // ---- phase 1: load + count tail takes ----
    unsigned clo = 0, chi = 0;
    #pragma unroll
    for (int e4 = 0; e4 < KPT / 4; ++e4) {
        float4 w = x4[e4 * NT + t];
        clo += (w.x < TLO) + (w.y < TLO) + (w.z < TLO) + (w.w < TLO);
        chi += (w.x > THI) + (w.y > THI) + (w.z > THI) + (w.w > THI);
    }

    // ---- phase 2: block exclusive scan of packed (clo | chi<<16) ----
    unsigned packed = clo | (chi << 16);
    unsigned incl = packed;
    #pragma unroll
    for (int off = 1; off < 32; off <<= 1) {
        unsigned v = __shfl_up_sync(0xffffffffu, incl, off);
        if (lane >= off) incl += v;
    }
    if (lane == 31) wsum[wid] = incl;
    __syncthreads();
    unsigned wbase = 0, tot = 0;
    #pragma unroll
    for (int w = 0; w < 8; ++w) {
        unsigned s = wsum[w];
        wbase += (w < wid) ? s : 0u;
        tot   += s;
    }
    unsigned excl   = wbase + incl - packed;
    unsigned baselo = excl & 0xFFFFu, basehi = excl >> 16;
    unsigned totlo  = tot  & 0xFFFFu, tothi  = tot  >> 16;

    const bool ok_lo = (totlo >= 513u && totlo <= 1024u);
    const bool ok_hi = (tothi >= 513u && tothi <= 1024u);

    // ---- phase 3: re-read row (cache-hot), scatter floats directly ----
    if (ok_lo && ok_hi) {
        unsigned plo = baselo, phi = basehi;
        #pragma unroll
        for (int e4 = 0; e4 < KPT / 4; ++e4) {
            float4 w = x4[e4 * NT + t];
            float fa[4] = { w.x, w.y, w.z, w.w };
            #pragma unroll
            for (int q = 0; q < 4; ++q) {
                float f = fa[q];
                if (f < TLO)      scratch[plo++] = f;
                else if (f > THI) scratch[1024 + phi++] = f;
            }
        }
    }
    __syncthreads();

    unsigned c0 = totlo, c1 = tothi;
    if (!ok_lo) {                                   // exact fallback (cold)
        unsigned Kcut;
        if (block_count(x4, 0u, false, &s_c, t) >= 513u) {
            Kcut = 0u;
        } else {
            unsigned X = 0;
            for (int b = 31; b >= 0; --b) {
                unsigned X2 = X | (1u << b);
                if (block_count(x4, X2, false, &s_c, t) < 513u) X = X2;
            }
            Kcut = X + 1u;
        }
        c0 = gather_side(x4, Kcut, 0, scratch, &s_c, t);
        float fK = key2f(Kcut);
        for (int i = (int)c0 + t; i < 513; i += NT) scratch[i] = fK;
        c0 = 513u;
    }
    if (!ok_hi) {
        unsigned Y = 0;
        for (int b = 31; b >= 0; --b) {
            unsigned Y2 = Y | (1u << b);
            if (block_count(x4, Y2, true, &s_c, t) >= 513u) Y = Y2;
        }
        c1 = gather_side(x4, Y, 1, scratch + 1024, &s_c, t);
        float fY = key2f(Y);
        for (int i = (int)c1 + t; i < 513; i += NT) scratch[1024 + i] = fY;
        c1 = 513u;
    }
    for (int i = (int)c0 + t; i < 1024; i += NT) scratch[i]        = FINF;
    for (int i = (int)c1 + t; i < 1024; i += NT) scratch[1024 + i] = FNINF;
    if (t == 0) s_best = ~0ull;
    __syncthreads();

    // ---- phase 4: register-blocked bitonic, stages up to 512 ----
    float v[8];
    #pragma unroll
    for (int e = 0; e < 8; ++e) v[e] = scratch[t * 8 + e];

    batcher8f(v, (ts & 1) == 0);

    #pragma unroll
    for (int kk = 16; kk <= 512; kk <<= 1) {
        bool up = ((ts & (kk >> 3)) == 0);
        #pragma unroll
        for (int j = kk >> 1; j >= 8; j >>= 1) {
            int delta = j >> 3;
            if (delta >= 32) smem_pass(v, delta, up, t, ts, scratch);
            else             shfl_pass(v, delta, up, ts);
        }
        sort8f(v, up);
    }

    // ---- final merge stage kk=1024 (up = true), PRUNED (R15):
    smem_pass(v, 64, true, t, ts, scratch);       // separation (all threads)

    const bool need = (t < 128) ? (ts < 64) : (ts >= 64);   // warp-uniform

    float red = 0.0f;
    if (!need) {
        if (t < 128) {   // lo top half -> s[512] = min
            red = fminf(fminf(fminf(v[0], v[1]), fminf(v[2], v[3])),
                        fminf(fminf(v[4], v[5]), fminf(v[6], v[7])));
            #pragma unroll
            for (int off = 16; off; off >>= 1)
                red = fminf(red, __shfl_xor_sync(0xffffffffu, red, off));
        } else {         // hi bottom half -> s_hi[511] = max
            red = fmaxf(fmaxf(fmaxf(v[0], v[1]), fmaxf(v[2], v[3])),
                        fmaxf(fmaxf(v[4], v[5]), fmaxf(v[6], v[7])));
            #pragma unroll
            for (int off = 16; off; off >>= 1)
                red = fmaxf(red, __shfl_xor_sync(0xffffffffu, red, off));
        }
    }

    // delta-32 smem pass restricted to active halves (SoA staging; barriers by ALL)
    __syncthreads();
    if (need) {
        #pragma unroll
        for (int e = 0; e < 8; ++e) scratch[e * 256 + t] = v[e];
    }
    __syncthreads();
    if (need) {
        bool keepmin = ((ts & 32) == 0);          // warp-uniform
        int pt = t ^ 32;                          // partner also active
        if (keepmin) {
            #pragma unroll
            for (int e = 0; e < 8; ++e) v[e] = fminf(v[e], scratch[e * 256 + pt]);
        } else {
            #pragma unroll
            for (int e = 0; e < 8; ++e) v[e] = fmaxf(v[e], scratch[e * 256 + pt]);
        }
        shfl_pass(v, 16, true, ts);
        shfl_pass(v,  8, true, ts);
        shfl_pass(v,  4, true, ts);
        shfl_pass(v,  2, true, ts);
        shfl_pass(v,  1, true, ts);
        sort8f(v, true);
    }

    // writeback (element layout for conflict-free argmin reads) + boundaries
    __syncthreads();
    #pragma unroll
    for (int e = 0; e < 8; ++e) scratch[t * 8 + e] = v[e];
    if (!need && lane == 0) wred[wid] = red;      // wids 2,3 (lo-top) / 4,5 (hi-bot)
    __syncthreads();
    if (t == 0) {
        scratch[512]  = fminf(wred[2], wred[3]);  // lo s[512]
        scratch[1535] = fmaxf(wred[4], wred[5]);  // hi s[511] (= 1024+511)
    }
    __syncthreads();

    // ---- phase 5: lengths + first-index argmin ----
    unsigned long long best = ~0ull;
    for (int i = t; i < NWIN; i += NT) {
        float len = scratch[1024 + 511 + i] - scratch[i];
        unsigned long long p =
            ((unsigned long long)__float_as_uint(len) << 32) | (unsigned)i;
        best = (p < best) ? p : best;
    }
    #pragma unroll
    for (int off = 16; off; off >>= 1) {
        unsigned long long o = __shfl_down_sync(0xffffffffu, best, off);
        best = (o < best) ? o : best;
    }
    if (lane == 0) atomicMin(&s_best, best);
    __syncthreads();

    if (t == 0) {
        int idx = (int)(unsigned)(s_best & 0xffffffffu);
        out[row]        = scratch[idx];
        out[rows + row] = scratch[1024 + 511 + idx];
    }
}

extern "C" void kernel_launch(void* const* d_in, const int* in_sizes, int n_in,
                              void* d_out, int out_size) {
    const float* x = (const float*)d_in[0];
    float* out = (float*)d_out;
    int rows = in_sizes[0] / NCOLS;   // 4096
    recall_window_kernel<<<rows, NT>>>(x, out, rows);
}